// round 13
// baseline (speedup 1.0000x reference)
#include <cuda_runtime.h>
#include <cuda_fp16.h>
#include <math.h>

#define DET 512
#define NB  16
#define NT  180
#define NPH 90
#define CW  768   // padded column width: detector index range [-128, 640)

// packed quad-columns: [b][ph][i] = (h2(gF_t,gF_u), h2(dF_t,dF_u), h2(gR_t,gR_u), h2(dR_t,dR_u))
static __device__ uint4 g_pk[(size_t)NB * NPH * CW];

__device__ __forceinline__ unsigned int h2_to_u32(__half2 h) {
    return *reinterpret_cast<unsigned int*>(&h);
}
__device__ __forceinline__ __half2 u32_to_h2(unsigned int u) {
    return *reinterpret_cast<__half2*>(&u);
}

// ---------------------------------------------------------------------------
// Kernel 1 (fused): Ram-Lak filter (direct conv, closed-form kernel) for
// 6 angles = 3 mirror-phases per block, then pack fp16 quad-columns straight
// to g_pk. Eliminates the g_xf round-trip and the separate repack kernel.
// Tile r (0..29): phases {3r, 3r+1, 3r+2}; angle slots 0..2 = t(ph)=ph,
// slots 3..5 = u(ph) = (ph==0 ? 90 : 180-ph).
// ---------------------------------------------------------------------------
__global__ __launch_bounds__(512) void filter_pack_kernel(const float* __restrict__ x)
{
    const int b  = blockIdx.x;
    const int r  = blockIdx.y;               // 0..29
    const int p0 = 3 * r;
    const int tid = threadIdx.x;             // 0..511

    __shared__ __align__(16) float xs[DET][8];    // [m][angle slot], slots 6,7 unused
    __shared__ float Gt[DET];

    // angle table for the 6 slots
    int ang[6];
    #pragma unroll
    for (int q = 0; q < 3; q++) {
        int ph = p0 + q;
        ang[q]     = ph;
        ang[3 + q] = (ph == 0) ? 90 : (180 - ph);
    }

    // closed-form ramp kernel table
    {
        int k = tid;
        float v;
        if (k == 0)       v = 0.5f;
        else if (k & 1) { float fk = (float)k; v = -2.0f / (9.869604401089358f * fk * fk); }
        else              v = 0.0f;
        Gt[k] = v;
    }

    // load x[b][m][ang[a]] into xs[m][a]
    const float* xb = x + (size_t)b * DET * NT;
    for (int i = tid; i < DET * 6; i += 512) {
        int m = i >> 3;          // not valid for /6 — use exact mapping below
        (void)m;
        break;
    }
    {
        // exact mapping: i enumerates (m, a)
        for (int i = tid; i < DET * 6; i += 512) {
            int m = i / 6;
            int a = i - 6 * m;
            xs[m][a] = xb[m * NT + ang[a]];
        }
    }
    __syncthreads();

    // convolution: out[d][a] = 0.5*x[d][a] + sum_{m opp parity} G[|d-m|] x[m][a]
    const int d = tid;
    float acc[6];
    {
        float4 v0 = *(const float4*)&xs[d][0];
        float2 v1 = *(const float2*)&xs[d][4];
        acc[0] = 0.5f * v0.x; acc[1] = 0.5f * v0.y; acc[2] = 0.5f * v0.z;
        acc[3] = 0.5f * v0.w; acc[4] = 0.5f * v1.x; acc[5] = 0.5f * v1.y;
    }
    const int m0 = (d & 1) ^ 1;
    for (int j = 0; j < 256; j++) {
        int m = m0 + 2 * j;
        int k = d - m; k = (k < 0) ? -k : k;
        float gv = Gt[k];
        float4 v0 = *(const float4*)&xs[m][0];
        float2 v1 = *(const float2*)&xs[m][4];
        acc[0] = fmaf(gv, v0.x, acc[0]);
        acc[1] = fmaf(gv, v0.y, acc[1]);
        acc[2] = fmaf(gv, v0.z, acc[2]);
        acc[3] = fmaf(gv, v0.w, acc[3]);
        acc[4] = fmaf(gv, v1.x, acc[4]);
        acc[5] = fmaf(gv, v1.y, acc[5]);
    }
    __syncthreads();     // everyone done reading xs

    // write filtered columns back into xs (same [m][a] layout)
    #pragma unroll
    for (int a = 0; a < 6; a++) xs[d][a] = acc[a];
    __syncthreads();

    // pack quad-columns for the 3 phases.
    // Gp[i] = (128 <= i < 640) ? fs[i-128] : 0
    #pragma unroll
    for (int q = 0; q < 3; q++) {
        uint4* dst = g_pk + ((size_t)b * NPH + p0 + q) * CW;
        for (int i = tid; i < CW; i += 512) {
            int dF  = i - 128;
            int dFp = i - 127;           // i+1 - 128
            int dR  = 639 - i;           // 767-i - 128
            int dR2 = 638 - i;           // 766-i - 128
            bool inF  = (unsigned)dF  < DET;
            bool inFp = (unsigned)dFp < DET;
            bool inR  = (unsigned)dR  < DET;
            bool inR2 = (unsigned)dR2 < DET;
            float gFt = inF  ? xs[dF][q]      : 0.0f;
            float gFu = inF  ? xs[dF][3 + q]  : 0.0f;
            float pFt = inFp ? xs[dFp][q]     : 0.0f;
            float pFu = inFp ? xs[dFp][3 + q] : 0.0f;
            float gRt = inR  ? xs[dR][q]      : 0.0f;
            float gRu = inR  ? xs[dR][3 + q]  : 0.0f;
            float pRt = inR2 ? xs[dR2][q]     : 0.0f;
            float pRu = inR2 ? xs[dR2][3 + q] : 0.0f;
            uint4 e;
            e.x = h2_to_u32(__floats2half2_rn(gFt,       gFu));
            e.y = h2_to_u32(__floats2half2_rn(pFt - gFt, pFu - gFu));
            e.z = h2_to_u32(__floats2half2_rn(gRt,       gRu));
            e.w = h2_to_u32(__floats2half2_rn(pRt - gRt, pRu - gRu));
            dst[i] = e;
        }
    }
}

// ---------------------------------------------------------------------------
// Kernel 2: backprojection over one quadrant; 4 mirror pixels x angle pair
// = 8 taps from 2 LDS.128 lookups. (Unchanged from Round 12.)
// ---------------------------------------------------------------------------
#define TAPIDX(iy, i0, w)                                    \
    {   float _tm = __fadd_rd((iy), MAGIC);                  \
        (i0) = __float_as_int(_tm) & 0x3FF;                  \
        (w)  = (iy) - (_tm - MAGIC); }

__global__ __launch_bounds__(256, 7) void backproj_kernel(float* __restrict__ out)
{
    const int b  = blockIdx.z;
    const int x0 = blockIdx.x * 32;          // quadrant j tile [x0, x0+32), < 256
    const int y0 = blockIdx.y * 32;          // quadrant i tile [y0, y0+32), < 256
    const int tid = threadIdx.x;             // 0..255
    const int tx = tid & 31;
    const int ty = tid >> 5;                 // 0..7 ; i = y0+ty+8k, k<4

    __shared__ __align__(16) uint4 col[2][CW];
    __shared__ float2 cs[NPH];

    if (tid < NPH) {
        float rad = (float)tid * 0.017453292519943295f;
        float sv, cv;
        sincosf(rad, &sv, &cv);
        cs[tid] = make_float2(cv, sv);
    }

    const uint4* pkb = g_pk + (size_t)b * NPH * CW;

    #pragma unroll
    for (int r = 0; r < 3; r++) col[0][tid + r * 256] = pkb[tid + r * 256];
    __syncthreads();

    float accA[4], accB[4], accC[4], accD[4];
    #pragma unroll
    for (int k = 0; k < 4; k++) { accA[k]=0.f; accB[k]=0.f; accC[k]=0.f; accD[k]=0.f; }

    const float fx = (float)(x0 + tx) - 255.5f;   // = 256*u_j, always < 0
    const float fy = (float)(y0 + ty) - 255.5f;   // = 256*u_i (base), always < 0
    const float lim = 65408.0f;                   // (1 - 1/512) * 256^2
    const float MAGIC = 8388608.0f;               // 2^23

    const float fxmin = 255.5f - (float)(x0 + 31);
    const float fymin = 255.5f - (float)(y0 + 31);
    const bool active = (fxmin * fxmin + fymin * fymin) <= lim;

    for (int ph = 0; ph < NPH; ph++) {
        const int cur = ph & 1;
        {
            int pn = (ph + 1 < NPH) ? ph + 1 : ph;
            const uint4* src = pkb + (size_t)pn * CW;
            uint4* dstc = col[cur ^ 1];
            #pragma unroll
            for (int r = 0; r < 3; r++) dstc[tid + r * 256] = src[tid + r * 256];
        }

        if (active) {
            const uint4* cp = col[cur];
            if (ph == 0) {
                float w; int i0; uint4 q;
                float iyj = fx + 383.5f;
                TAPIDX(iyj, i0, w); q = cp[i0];
                __half2 w2 = __float2half2_rn(w);
                float tf0 = __low2float(__hfma2(w2, u32_to_h2(q.y), u32_to_h2(q.x)));
                float tr0 = __low2float(__hfma2(w2, u32_to_h2(q.w), u32_to_h2(q.z)));
                #pragma unroll
                for (int k = 0; k < 4; k++) {
                    float iyi = (fy + 8.0f * (float)k) + 383.5f;
                    TAPIDX(iyi, i0, w); q = cp[i0];
                    __half2 wk = __float2half2_rn(w);
                    float tf9 = __high2float(__hfma2(wk, u32_to_h2(q.y), u32_to_h2(q.x)));
                    float tr9 = __high2float(__hfma2(wk, u32_to_h2(q.w), u32_to_h2(q.z)));
                    accA[k] += tf0 + tr9;
                    accB[k] += tr0 + tr9;
                    accC[k] += tr0 + tf9;
                    accD[k] += tf0 + tf9;
                }
            } else {
                const float2 cst = cs[ph];
                const float c = cst.x, s = cst.y;
                const float base1 = fmaf(c, fx, fmaf(-s, fy, 383.5f)); // t1 = ujc - uis
                const float base2 = fmaf(c, fx, fmaf( s, fy, 383.5f)); // t2 = ujc + uis
                const float s8 = 8.0f * s;
                #pragma unroll
                for (int k = 0; k < 4; k++) {
                    float w; int i0; uint4 q;
                    float iy1 = fmaf(-s8, (float)k, base1);
                    TAPIDX(iy1, i0, w); q = cp[i0];
                    {
                        __half2 w2 = __float2half2_rn(w);
                        __half2 vf = __hfma2(w2, u32_to_h2(q.y), u32_to_h2(q.x));
                        __half2 vr = __hfma2(w2, u32_to_h2(q.w), u32_to_h2(q.z));
                        accA[k] += __low2float(vf);
                        accB[k] += __high2float(vf);
                        accC[k] += __low2float(vr);
                        accD[k] += __high2float(vr);
                    }
                    float iy2 = fmaf(s8, (float)k, base2);
                    TAPIDX(iy2, i0, w); q = cp[i0];
                    {
                        __half2 w2 = __float2half2_rn(w);
                        __half2 vf = __hfma2(w2, u32_to_h2(q.y), u32_to_h2(q.x));
                        __half2 vr = __hfma2(w2, u32_to_h2(q.w), u32_to_h2(q.z));
                        accD[k] += __low2float(vf);
                        accC[k] += __high2float(vf);
                        accB[k] += __low2float(vr);
                        accA[k] += __high2float(vr);
                    }
                }
            }
        }
        __syncthreads();
    }

    const float scale = 0.008726646259971648f;   // pi/360
    float* ob = out + (size_t)b * DET * DET;
    const int x1 = x0 + tx;
    const int x2 = 511 - x1;
    #pragma unroll
    for (int k = 0; k < 4; k++) {
        int   py  = y0 + ty + 8 * k;
        int   qy  = 511 - py;
        float fyk = fy + 8.0f * (float)k;
        float m   = ((fx * fx + fyk * fyk) <= lim) ? scale : 0.0f;
        ob[(size_t)py * DET + x1] = accA[k] * m;
        ob[(size_t)py * DET + x2] = accB[k] * m;
        ob[(size_t)qy * DET + x2] = accC[k] * m;
        ob[(size_t)qy * DET + x1] = accD[k] * m;
    }
}

extern "C" void kernel_launch(void* const* d_in, const int* in_sizes, int n_in,
                              void* d_out, int out_size)
{
    const float* x = (const float*)d_in[0];
    float* out = (float*)d_out;

    dim3 gf(NB, 30);          // 16 batches x 30 tiles (3 phases / 6 angles each)
    filter_pack_kernel<<<gf, 512>>>(x);

    dim3 gb(8, 8, NB);        // quadrant: 8x8 tiles of 32x32, per batch
    backproj_kernel<<<gb, 256>>>(out);
}

// round 14
// speedup vs baseline: 1.1553x; 1.1553x over previous
#include <cuda_runtime.h>
#include <cuda_fp16.h>
#include <math.h>

#define DET 512
#define NB  16
#define NT  180
#define NPH 90
#define CW  768   // padded column width: detector index range [-128, 640)

// filtered sinogram, layout [b][t][d]
static __device__ float g_xf[(size_t)NB * NT * DET];
// packed quad-columns: [b][ph][i] = (h2(gF_t,gF_u), h2(dF_t,dF_u), h2(gR_t,gR_u), h2(dR_t,dR_u))
static __device__ uint4 g_pk[(size_t)NB * NPH * CW];

__device__ __forceinline__ unsigned int h2_to_u32(__half2 h) {
    return *reinterpret_cast<unsigned int*>(&h);
}
__device__ __forceinline__ __half2 u32_to_h2(unsigned int u) {
    return *reinterpret_cast<__half2*>(&u);
}

// ---------------------------------------------------------------------------
// Kernel 1: Ram-Lak filtering as direct convolution (tile-8, R12 proven)
// ---------------------------------------------------------------------------
__global__ __launch_bounds__(512) void filter_kernel(const float* __restrict__ x)
{
    const int b  = blockIdx.x;
    const int t0 = blockIdx.y * 8;
    const int tid = threadIdx.x;            // 0..511

    __shared__ __align__(16) float xs[DET][8];
    __shared__ float Gt[DET];

    {
        int k = tid;
        float v;
        if (k == 0)       v = 0.5f;
        else if (k & 1) { float fk = (float)k; v = -2.0f / (9.869604401089358f * fk * fk); }
        else              v = 0.0f;
        Gt[k] = v;
    }

    const float* xb = x + (size_t)b * DET * NT;
    const int tt = tid & 7;
    const int mb = tid >> 3;                 // 0..63
    const int tg0 = t0 + tt;
    #pragma unroll
    for (int p = 0; p < 8; p++) {
        int m = mb + p * 64;
        xs[m][tt] = (tg0 < NT) ? xb[m * NT + tg0] : 0.0f;
    }
    __syncthreads();

    const int d = tid;
    float4 acc[2];
    {
        const float4* xd = (const float4*)xs[d];
        #pragma unroll
        for (int q = 0; q < 2; q++) {
            float4 v = xd[q];
            acc[q].x = 0.5f * v.x; acc[q].y = 0.5f * v.y;
            acc[q].z = 0.5f * v.z; acc[q].w = 0.5f * v.w;
        }
    }

    const int m0 = (d & 1) ^ 1;
    for (int j = 0; j < 256; j++) {
        int m = m0 + 2 * j;
        int k = d - m; k = (k < 0) ? -k : k;
        float gv = Gt[k];
        const float4* xm = (const float4*)xs[m];
        #pragma unroll
        for (int q = 0; q < 2; q++) {
            float4 v = xm[q];
            acc[q].x = fmaf(gv, v.x, acc[q].x);
            acc[q].y = fmaf(gv, v.y, acc[q].y);
            acc[q].z = fmaf(gv, v.z, acc[q].z);
            acc[q].w = fmaf(gv, v.w, acc[q].w);
        }
    }

    float vals[8];
    #pragma unroll
    for (int q = 0; q < 2; q++) {
        vals[q*4+0] = acc[q].x; vals[q*4+1] = acc[q].y;
        vals[q*4+2] = acc[q].z; vals[q*4+3] = acc[q].w;
    }
    #pragma unroll
    for (int r = 0; r < 8; r++) {
        int tg = t0 + r;
        if (tg < NT) g_xf[((size_t)b * NT + tg) * DET + d] = vals[r];
    }
}

// ---------------------------------------------------------------------------
// Kernel 1b: repack into padded forward+reversed fp16 quad-columns.
// ph=0 -> angles {0, 90}; ph in 1..89 -> {ph, 180-ph}.
// ---------------------------------------------------------------------------
__global__ __launch_bounds__(256) void repack_kernel()
{
    const int b  = blockIdx.x;
    const int ph = blockIdx.y;
    const int t = (ph == 0) ? 0  : ph;
    const int u = (ph == 0) ? 90 : (180 - ph);

    const float* st = g_xf + ((size_t)b * NT + t) * DET;
    const float* su = g_xf + ((size_t)b * NT + u) * DET;
    uint4* dst = g_pk + ((size_t)b * NPH + ph) * CW;

    __shared__ float Gt[CW], Gu[CW];
    for (int i = threadIdx.x; i < CW; i += 256) {
        int d = i - 128;
        bool in = (d >= 0) && (d < DET);
        Gt[i] = in ? st[d] : 0.0f;
        Gu[i] = in ? su[d] : 0.0f;
    }
    __syncthreads();

    for (int i = threadIdx.x; i < CW; i += 256) {
        int ip  = (i + 1 < CW) ? i + 1 : CW - 1;
        int ir  = CW - 1 - i;
        int ir2 = (766 - i >= 0) ? 766 - i : 0;
        uint4 e;
        e.x = h2_to_u32(__floats2half2_rn(Gt[i],           Gu[i]));
        e.y = h2_to_u32(__floats2half2_rn(Gt[ip] - Gt[i],  Gu[ip] - Gu[i]));
        e.z = h2_to_u32(__floats2half2_rn(Gt[ir],          Gu[ir]));
        e.w = h2_to_u32(__floats2half2_rn(Gt[ir2] - Gt[ir], Gu[ir2] - Gu[ir]));
        dst[i] = e;
    }
}

// ---------------------------------------------------------------------------
// Kernel 2: backprojection over one quadrant; 4 mirror pixels x angle pair
// = 8 taps from 2 LDS.128 lookups. 512 threads / 32x64 tile: halves the
// per-batch column-prefetch traffic vs 256-thread blocks.
// ---------------------------------------------------------------------------
#define TAPIDX(iy, i0, w)                                    \
    {   float _tm = __fadd_rd((iy), MAGIC);                  \
        (i0) = __float_as_int(_tm) & 0x3FF;                  \
        (w)  = (iy) - (_tm - MAGIC); }

__global__ __launch_bounds__(512, 4) void backproj_kernel(float* __restrict__ out)
{
    const int b  = blockIdx.z;
    const int x0 = blockIdx.x * 32;          // quadrant j tile [x0, x0+32), < 256
    const int y0 = blockIdx.y * 64;          // quadrant i tile [y0, y0+64), < 256
    const int tid = threadIdx.x;             // 0..511
    const int tx = tid & 31;
    const int ty = tid >> 5;                 // 0..15 ; i = y0+ty+16k, k<4

    __shared__ __align__(16) uint4 col[2][CW];
    __shared__ float2 cs[NPH];

    if (tid < NPH) {
        float rad = (float)tid * 0.017453292519943295f;
        float sv, cv;
        sincosf(rad, &sv, &cv);
        cs[tid] = make_float2(cv, sv);
    }

    const uint4* pkb = g_pk + (size_t)b * NPH * CW;

    // preload phase 0 (768 = 512 + 256)
    col[0][tid] = pkb[tid];
    if (tid < CW - 512) col[0][tid + 512] = pkb[tid + 512];
    __syncthreads();

    float accA[4], accB[4], accC[4], accD[4];
    #pragma unroll
    for (int k = 0; k < 4; k++) { accA[k]=0.f; accB[k]=0.f; accC[k]=0.f; accD[k]=0.f; }

    const float fx = (float)(x0 + tx) - 255.5f;   // = 256*u_j, always < 0
    const float fy = (float)(y0 + ty) - 255.5f;   // = 256*u_i (base), always < 0
    const float lim = 65408.0f;                   // (1 - 1/512) * 256^2
    const float MAGIC = 8388608.0f;               // 2^23

    // block-uniform circle skip
    const float fxmin = 255.5f - (float)(x0 + 31);
    const float fymin = 255.5f - (float)(y0 + 63);
    const bool active = (fxmin * fxmin + fymin * fymin) <= lim;

    for (int ph = 0; ph < NPH; ph++) {
        const int cur = ph & 1;
        {
            int pn = (ph + 1 < NPH) ? ph + 1 : ph;
            const uint4* src = pkb + (size_t)pn * CW;
            uint4* dstc = col[cur ^ 1];
            dstc[tid] = src[tid];
            if (tid < CW - 512) dstc[tid + 512] = src[tid + 512];
        }

        if (active) {
            const uint4* cp = col[cur];
            if (ph == 0) {
                // lanes: low = angle 0, high = angle 90
                float w; int i0; uint4 q;
                float iyj = fx + 383.5f;
                TAPIDX(iyj, i0, w); q = cp[i0];
                __half2 w2 = __float2half2_rn(w);
                float tf0 = __low2float(__hfma2(w2, u32_to_h2(q.y), u32_to_h2(q.x)));
                float tr0 = __low2float(__hfma2(w2, u32_to_h2(q.w), u32_to_h2(q.z)));
                #pragma unroll
                for (int k = 0; k < 4; k++) {
                    float iyi = (fy + 16.0f * (float)k) + 383.5f;
                    TAPIDX(iyi, i0, w); q = cp[i0];
                    __half2 wk = __float2half2_rn(w);
                    float tf9 = __high2float(__hfma2(wk, u32_to_h2(q.y), u32_to_h2(q.x)));
                    float tr9 = __high2float(__hfma2(wk, u32_to_h2(q.w), u32_to_h2(q.z)));
                    accA[k] += tf0 + tr9;
                    accB[k] += tr0 + tr9;
                    accC[k] += tr0 + tf9;
                    accD[k] += tf0 + tf9;
                }
            } else {
                const float2 cst = cs[ph];
                const float c = cst.x, s = cst.y;
                const float base1 = fmaf(c, fx, fmaf(-s, fy, 383.5f)); // t1 = ujc - uis
                const float base2 = fmaf(c, fx, fmaf( s, fy, 383.5f)); // t2 = ujc + uis
                const float s16 = 16.0f * s;
                #pragma unroll
                for (int k = 0; k < 4; k++) {
                    float w; int i0; uint4 q;
                    // lookup 1: fwd -> (A@t, B@u); rev -> (C@t, D@u)
                    float iy1 = fmaf(-s16, (float)k, base1);
                    TAPIDX(iy1, i0, w); q = cp[i0];
                    {
                        __half2 w2 = __float2half2_rn(w);
                        __half2 vf = __hfma2(w2, u32_to_h2(q.y), u32_to_h2(q.x));
                        __half2 vr = __hfma2(w2, u32_to_h2(q.w), u32_to_h2(q.z));
                        accA[k] += __low2float(vf);
                        accB[k] += __high2float(vf);
                        accC[k] += __low2float(vr);
                        accD[k] += __high2float(vr);
                    }
                    // lookup 2: fwd -> (D@t, C@u); rev -> (B@t, A@u)
                    float iy2 = fmaf(s16, (float)k, base2);
                    TAPIDX(iy2, i0, w); q = cp[i0];
                    {
                        __half2 w2 = __float2half2_rn(w);
                        __half2 vf = __hfma2(w2, u32_to_h2(q.y), u32_to_h2(q.x));
                        __half2 vr = __hfma2(w2, u32_to_h2(q.w), u32_to_h2(q.z));
                        accD[k] += __low2float(vf);
                        accC[k] += __high2float(vf);
                        accB[k] += __low2float(vr);
                        accA[k] += __high2float(vr);
                    }
                }
            }
        }
        __syncthreads();
    }

    // epilogue: circle mask (symmetric across the quad) + pi/360 scale
    const float scale = 0.008726646259971648f;
    float* ob = out + (size_t)b * DET * DET;
    const int x1 = x0 + tx;
    const int x2 = 511 - x1;
    #pragma unroll
    for (int k = 0; k < 4; k++) {
        int   py  = y0 + ty + 16 * k;
        int   qy  = 511 - py;
        float fyk = fy + 16.0f * (float)k;
        float m   = ((fx * fx + fyk * fyk) <= lim) ? scale : 0.0f;
        ob[(size_t)py * DET + x1] = accA[k] * m;
        ob[(size_t)py * DET + x2] = accB[k] * m;
        ob[(size_t)qy * DET + x2] = accC[k] * m;
        ob[(size_t)qy * DET + x1] = accD[k] * m;
    }
}

extern "C" void kernel_launch(void* const* d_in, const int* in_sizes, int n_in,
                              void* d_out, int out_size)
{
    const float* x = (const float*)d_in[0];
    float* out = (float*)d_out;

    dim3 gf(NB, 23);          // 16 batches x ceil(180/8) angle tiles
    filter_kernel<<<gf, 512>>>(x);

    dim3 gr(NB, NPH);         // quad-column pack per (batch, phase)
    repack_kernel<<<gr, 256>>>();

    dim3 gb(8, 4, NB);        // quadrant: 8x4 tiles of 32x64, per batch
    backproj_kernel<<<gb, 512>>>(out);
}

// round 15
// speedup vs baseline: 1.2393x; 1.0727x over previous
#include <cuda_runtime.h>
#include <cuda_fp16.h>
#include <math.h>

#define DET 512
#define NB  16
#define NT  180
#define NPH 90
#define CW  768   // padded column width: detector index range [-128, 640)

// filtered sinogram, layout [b][t][d]
static __device__ float g_xf[(size_t)NB * NT * DET];
// packed quad-columns: [b][ph][i] = (h2(gF_t,gF_u), h2(dF_t,dF_u), h2(gR_t,gR_u), h2(dR_t,dR_u))
static __device__ uint4 g_pk[(size_t)NB * NPH * CW];

__device__ __forceinline__ unsigned int h2_to_u32(__half2 h) {
    return *reinterpret_cast<unsigned int*>(&h);
}
__device__ __forceinline__ __half2 u32_to_h2(unsigned int u) {
    return *reinterpret_cast<__half2*>(&u);
}

// ---------------------------------------------------------------------------
// Kernel 1: Ram-Lak filter, register-tiled: 256 threads, each computes
// 4 d-values (stride 128, same parity) x 4 angles. Signed kernel table
// gsym[j] = G(2j-511) makes the 4 taps per thread stride-64 scalar loads
// that are stride-1 (conflict-free) across the warp.
// ---------------------------------------------------------------------------
__global__ __launch_bounds__(256) void filter_kernel(const float* __restrict__ x)
{
    const int b  = blockIdx.x;
    const int t0 = blockIdx.y * 8;
    const int tid = threadIdx.x;             // 0..255

    __shared__ __align__(16) float xs[DET][8];    // [m][angle slot]
    __shared__ float gsym[DET];                   // G(k), k = 2j-511 (odd)

    for (int j = tid; j < DET; j += 256) {
        float k = (float)(2 * j - 511);
        gsym[j] = -2.0f / (9.869604401089358f * k * k);
    }

    const float* xb = x + (size_t)b * DET * NT;
    const int tt = tid & 7;
    const int mb = tid >> 3;                  // 0..31
    const int tg0 = t0 + tt;
    #pragma unroll
    for (int p = 0; p < 16; p++) {
        int m = mb + p * 32;
        xs[m][tt] = (tg0 < NT) ? xb[m * NT + tg0] : 0.0f;
    }
    __syncthreads();

    // decomposition: ah = angle half (0/4); par = parity; grp = d group
    const int ah  = (tid >> 7) * 4;           // angles ah..ah+3
    const int t7  = tid & 127;
    const int par = t7 >> 6;                  // 0/1
    const int grp = t7 & 63;                  // 0..63
    // d_r = par + 2*grp + 128*r, r = 0..3
    const int dbase = par + 2 * grp;

    float acc[4][4];
    #pragma unroll
    for (int r = 0; r < 4; r++) {
        const float* xr = &xs[dbase + 128 * r][ah];
        #pragma unroll
        for (int a = 0; a < 4; a++) acc[r][a] = 0.5f * xr[a];
    }

    // m scans opposite parity; gsym idx for (d_r, m): par+grp+255-j + 64r
    const int mp = 1 - par;
    const int gb0 = par + grp + 255;
    for (int j = 0; j < 256; j++) {
        const int m = mp + 2 * j;
        const int gb = gb0 - j;
        float g0 = gsym[gb];
        float g1 = gsym[gb + 64];
        float g2 = gsym[gb + 128];
        float g3 = gsym[gb + 192];
        float4 xv = *(const float4*)&xs[m][ah];
        acc[0][0] = fmaf(g0, xv.x, acc[0][0]);
        acc[0][1] = fmaf(g0, xv.y, acc[0][1]);
        acc[0][2] = fmaf(g0, xv.z, acc[0][2]);
        acc[0][3] = fmaf(g0, xv.w, acc[0][3]);
        acc[1][0] = fmaf(g1, xv.x, acc[1][0]);
        acc[1][1] = fmaf(g1, xv.y, acc[1][1]);
        acc[1][2] = fmaf(g1, xv.z, acc[1][2]);
        acc[1][3] = fmaf(g1, xv.w, acc[1][3]);
        acc[2][0] = fmaf(g2, xv.x, acc[2][0]);
        acc[2][1] = fmaf(g2, xv.y, acc[2][1]);
        acc[2][2] = fmaf(g2, xv.z, acc[2][2]);
        acc[2][3] = fmaf(g2, xv.w, acc[2][3]);
        acc[3][0] = fmaf(g3, xv.x, acc[3][0]);
        acc[3][1] = fmaf(g3, xv.y, acc[3][1]);
        acc[3][2] = fmaf(g3, xv.z, acc[3][2]);
        acc[3][3] = fmaf(g3, xv.w, acc[3][3]);
    }

    #pragma unroll
    for (int r = 0; r < 4; r++) {
        int d = dbase + 128 * r;
        #pragma unroll
        for (int a = 0; a < 4; a++) {
            int tg = t0 + ah + a;
            if (tg < NT) g_xf[((size_t)b * NT + tg) * DET + d] = acc[r][a];
        }
    }
}

// ---------------------------------------------------------------------------
// Kernel 1b: repack into padded forward+reversed fp16 quad-columns.
// ph=0 -> angles {0, 90}; ph in 1..89 -> {ph, 180-ph}.
// ---------------------------------------------------------------------------
__global__ __launch_bounds__(256) void repack_kernel()
{
    const int b  = blockIdx.x;
    const int ph = blockIdx.y;
    const int t = (ph == 0) ? 0  : ph;
    const int u = (ph == 0) ? 90 : (180 - ph);

    const float* st = g_xf + ((size_t)b * NT + t) * DET;
    const float* su = g_xf + ((size_t)b * NT + u) * DET;
    uint4* dst = g_pk + ((size_t)b * NPH + ph) * CW;

    __shared__ float Gt[CW], Gu[CW];
    for (int i = threadIdx.x; i < CW; i += 256) {
        int d = i - 128;
        bool in = (d >= 0) && (d < DET);
        Gt[i] = in ? st[d] : 0.0f;
        Gu[i] = in ? su[d] : 0.0f;
    }
    __syncthreads();

    for (int i = threadIdx.x; i < CW; i += 256) {
        int ip  = (i + 1 < CW) ? i + 1 : CW - 1;
        int ir  = CW - 1 - i;
        int ir2 = (766 - i >= 0) ? 766 - i : 0;
        uint4 e;
        e.x = h2_to_u32(__floats2half2_rn(Gt[i],           Gu[i]));
        e.y = h2_to_u32(__floats2half2_rn(Gt[ip] - Gt[i],  Gu[ip] - Gu[i]));
        e.z = h2_to_u32(__floats2half2_rn(Gt[ir],          Gu[ir]));
        e.w = h2_to_u32(__floats2half2_rn(Gt[ir2] - Gt[ir], Gu[ir2] - Gu[ir]));
        dst[i] = e;
    }
}

// ---------------------------------------------------------------------------
// Kernel 2: backprojection (unchanged from Round 14 best).
// ---------------------------------------------------------------------------
#define TAPIDX(iy, i0, w)                                    \
    {   float _tm = __fadd_rd((iy), MAGIC);                  \
        (i0) = __float_as_int(_tm) & 0x3FF;                  \
        (w)  = (iy) - (_tm - MAGIC); }

__global__ __launch_bounds__(512, 4) void backproj_kernel(float* __restrict__ out)
{
    const int b  = blockIdx.z;
    const int x0 = blockIdx.x * 32;
    const int y0 = blockIdx.y * 64;
    const int tid = threadIdx.x;             // 0..511
    const int tx = tid & 31;
    const int ty = tid >> 5;                 // 0..15 ; i = y0+ty+16k, k<4

    __shared__ __align__(16) uint4 col[2][CW];
    __shared__ float2 cs[NPH];

    if (tid < NPH) {
        float rad = (float)tid * 0.017453292519943295f;
        float sv, cv;
        sincosf(rad, &sv, &cv);
        cs[tid] = make_float2(cv, sv);
    }

    const uint4* pkb = g_pk + (size_t)b * NPH * CW;

    col[0][tid] = pkb[tid];
    if (tid < CW - 512) col[0][tid + 512] = pkb[tid + 512];
    __syncthreads();

    float accA[4], accB[4], accC[4], accD[4];
    #pragma unroll
    for (int k = 0; k < 4; k++) { accA[k]=0.f; accB[k]=0.f; accC[k]=0.f; accD[k]=0.f; }

    const float fx = (float)(x0 + tx) - 255.5f;
    const float fy = (float)(y0 + ty) - 255.5f;
    const float lim = 65408.0f;
    const float MAGIC = 8388608.0f;

    const float fxmin = 255.5f - (float)(x0 + 31);
    const float fymin = 255.5f - (float)(y0 + 63);
    const bool active = (fxmin * fxmin + fymin * fymin) <= lim;

    for (int ph = 0; ph < NPH; ph++) {
        const int cur = ph & 1;
        {
            int pn = (ph + 1 < NPH) ? ph + 1 : ph;
            const uint4* src = pkb + (size_t)pn * CW;
            uint4* dstc = col[cur ^ 1];
            dstc[tid] = src[tid];
            if (tid < CW - 512) dstc[tid + 512] = src[tid + 512];
        }

        if (active) {
            const uint4* cp = col[cur];
            if (ph == 0) {
                float w; int i0; uint4 q;
                float iyj = fx + 383.5f;
                TAPIDX(iyj, i0, w); q = cp[i0];
                __half2 w2 = __float2half2_rn(w);
                float tf0 = __low2float(__hfma2(w2, u32_to_h2(q.y), u32_to_h2(q.x)));
                float tr0 = __low2float(__hfma2(w2, u32_to_h2(q.w), u32_to_h2(q.z)));
                #pragma unroll
                for (int k = 0; k < 4; k++) {
                    float iyi = (fy + 16.0f * (float)k) + 383.5f;
                    TAPIDX(iyi, i0, w); q = cp[i0];
                    __half2 wk = __float2half2_rn(w);
                    float tf9 = __high2float(__hfma2(wk, u32_to_h2(q.y), u32_to_h2(q.x)));
                    float tr9 = __high2float(__hfma2(wk, u32_to_h2(q.w), u32_to_h2(q.z)));
                    accA[k] += tf0 + tr9;
                    accB[k] += tr0 + tr9;
                    accC[k] += tr0 + tf9;
                    accD[k] += tf0 + tf9;
                }
            } else {
                const float2 cst = cs[ph];
                const float c = cst.x, s = cst.y;
                const float base1 = fmaf(c, fx, fmaf(-s, fy, 383.5f));
                const float base2 = fmaf(c, fx, fmaf( s, fy, 383.5f));
                const float s16 = 16.0f * s;
                #pragma unroll
                for (int k = 0; k < 4; k++) {
                    float w; int i0; uint4 q;
                    float iy1 = fmaf(-s16, (float)k, base1);
                    TAPIDX(iy1, i0, w); q = cp[i0];
                    {
                        __half2 w2 = __float2half2_rn(w);
                        __half2 vf = __hfma2(w2, u32_to_h2(q.y), u32_to_h2(q.x));
                        __half2 vr = __hfma2(w2, u32_to_h2(q.w), u32_to_h2(q.z));
                        accA[k] += __low2float(vf);
                        accB[k] += __high2float(vf);
                        accC[k] += __low2float(vr);
                        accD[k] += __high2float(vr);
                    }
                    float iy2 = fmaf(s16, (float)k, base2);
                    TAPIDX(iy2, i0, w); q = cp[i0];
                    {
                        __half2 w2 = __float2half2_rn(w);
                        __half2 vf = __hfma2(w2, u32_to_h2(q.y), u32_to_h2(q.x));
                        __half2 vr = __hfma2(w2, u32_to_h2(q.w), u32_to_h2(q.z));
                        accD[k] += __low2float(vf);
                        accC[k] += __high2float(vf);
                        accB[k] += __low2float(vr);
                        accA[k] += __high2float(vr);
                    }
                }
            }
        }
        __syncthreads();
    }

    const float scale = 0.008726646259971648f;
    float* ob = out + (size_t)b * DET * DET;
    const int x1 = x0 + tx;
    const int x2 = 511 - x1;
    #pragma unroll
    for (int k = 0; k < 4; k++) {
        int   py  = y0 + ty + 16 * k;
        int   qy  = 511 - py;
        float fyk = fy + 16.0f * (float)k;
        float m   = ((fx * fx + fyk * fyk) <= lim) ? scale : 0.0f;
        ob[(size_t)py * DET + x1] = accA[k] * m;
        ob[(size_t)py * DET + x2] = accB[k] * m;
        ob[(size_t)qy * DET + x2] = accC[k] * m;
        ob[(size_t)qy * DET + x1] = accD[k] * m;
    }
}

extern "C" void kernel_launch(void* const* d_in, const int* in_sizes, int n_in,
                              void* d_out, int out_size)
{
    const float* x = (const float*)d_in[0];
    float* out = (float*)d_out;

    dim3 gf(NB, 23);          // 16 batches x ceil(180/8) angle tiles
    filter_kernel<<<gf, 256>>>(x);

    dim3 gr(NB, NPH);         // quad-column pack per (batch, phase)
    repack_kernel<<<gr, 256>>>();

    dim3 gb(8, 4, NB);        // quadrant: 8x4 tiles of 32x64, per batch
    backproj_kernel<<<gb, 512>>>(out);
}